// round 13
// baseline (speedup 1.0000x reference)
#include <cuda_runtime.h>

#define BATCH 262144
#define SDIM  100
#define HID   256
#define ENC   128
#define EXPH  64
#define ACTD  10
#define NK    10
#define GRID1 2048          // BATCH/128

typedef unsigned long long u64;

// ---- device-global scratch (no allocation allowed) ----
__device__ float g_h[BATCH * HID];
__device__ float g_enc[BATCH * ENC];
__device__ float g_psum[GRID1 * HID];
__device__ float g_psq [GRID1 * HID];
__device__ float g_scale[HID];
__device__ float g_shift[HID];

// ---- packed fp32x2 helpers (FFMA2 only reachable via PTX) ----
__device__ __forceinline__ u64 dupf(float w) {
    u64 d; asm("mov.b64 %0, {%1, %1};" : "=l"(d) : "f"(w)); return d;
}
__device__ __forceinline__ void fma2(u64 &a, u64 x, u64 y) {
    asm("fma.rn.f32x2 %0, %1, %2, %0;" : "+l"(a) : "l"(x), "l"(y));
}
__device__ __forceinline__ float2 unp(u64 v) {
    float2 r; asm("mov.b64 {%0, %1}, %2;" : "=f"(r.x), "=f"(r.y) : "l"(v)); return r;
}
__device__ __forceinline__ float ftanh(float x) {
    float v = fminf(fmaxf(x, -15.f), 15.f);
    float t = __expf(2.f * v);
    return __fdividef(t - 1.f, t + 1.f);
}

// =====================================================================
// K1: h = relu(state @ W1 + b1) + per-block column sum/sumsq
// grid (2048,2) x 256 thr. smem: st pairs [100][65]u64 | W1 [100][128] | b1
// =====================================================================
#define K1_SMEM (100*65*8 + 100*128*4 + 128*4)   // 52000+51200+512 = 103712

__global__ void __launch_bounds__(256) k1_gemm_relu(
    const float* __restrict__ state, const float* __restrict__ W1,
    const float* __restrict__ b1)
{
    extern __shared__ char sm[];
    float* stf = (float*)sm;                 // float view: k*130 + r
    u64*   st2 = (u64*)sm;                   // pair view:  k*65 + rp
    float* w1s = (float*)(sm + 52000);       // [100][128]
    float* b1s = (float*)(sm + 103200);

    const int tid  = threadIdx.x;
    const int row0 = blockIdx.x * 128;
    const int cb   = blockIdx.y;

    for (int idx = tid; idx < 128 * SDIM; idx += 256) {
        int r = idx / SDIM, k = idx - r * SDIM;
        stf[k * 130 + r] = state[(size_t)(row0 + r) * SDIM + k];
    }
    for (int idx = tid; idx < SDIM * 128; idx += 256) {
        int k = idx >> 7, c = idx & 127;
        w1s[idx] = W1[k * HID + cb * 128 + c];
    }
    if (tid < 128) b1s[tid] = b1[cb * 128 + tid];
    __syncthreads();

    const int tc = tid & 15, tr = tid >> 4;
    u64 acc[4][8];
    #pragma unroll
    for (int j = 0; j < 4; ++j)
        #pragma unroll
        for (int u = 0; u < 8; ++u) acc[j][u] = 0ull;

    #pragma unroll 2
    for (int k = 0; k < SDIM; ++k) {
        u64 p0 = st2[k * 65 + tr * 4 + 0];
        u64 p1 = st2[k * 65 + tr * 4 + 1];
        u64 p2 = st2[k * 65 + tr * 4 + 2];
        u64 p3 = st2[k * 65 + tr * 4 + 3];
        float4 wa = *(const float4*)(w1s + k * 128 + tc * 8);
        float4 wb = *(const float4*)(w1s + k * 128 + tc * 8 + 4);
        float wv[8] = {wa.x, wa.y, wa.z, wa.w, wb.x, wb.y, wb.z, wb.w};
        #pragma unroll
        for (int u = 0; u < 8; ++u) {
            u64 d = dupf(wv[u]);
            fma2(acc[0][u], p0, d); fma2(acc[1][u], p1, d);
            fma2(acc[2][u], p2, d); fma2(acc[3][u], p3, d);
        }
    }

    float csum[8], csq[8], bvals[8];
    #pragma unroll
    for (int u = 0; u < 8; ++u) { csum[u] = 0.f; csq[u] = 0.f; bvals[u] = b1s[tc * 8 + u]; }

    #pragma unroll
    for (int j = 0; j < 4; ++j) {
        float v0[8], v1[8];
        #pragma unroll
        for (int u = 0; u < 8; ++u) {
            float2 t = unp(acc[j][u]);
            float x0 = fmaxf(t.x + bvals[u], 0.f);
            float x1 = fmaxf(t.y + bvals[u], 0.f);
            v0[u] = x0; v1[u] = x1;
            csum[u] += x0 + x1;
            csq[u]  += x0 * x0 + x1 * x1;
        }
        int rg = row0 + tr * 8 + 2 * j;
        float* hp = g_h + (size_t)rg * HID + cb * 128 + tc * 8;
        *(float4*)hp       = make_float4(v0[0], v0[1], v0[2], v0[3]);
        *(float4*)(hp + 4) = make_float4(v0[4], v0[5], v0[6], v0[7]);
        hp += HID;
        *(float4*)hp       = make_float4(v1[0], v1[1], v1[2], v1[3]);
        *(float4*)(hp + 4) = make_float4(v1[4], v1[5], v1[6], v1[7]);
    }

    __syncthreads();
    float* red = (float*)sm;                 // alias, [16][128]
    #pragma unroll
    for (int u = 0; u < 8; ++u) red[tr * 128 + tc * 8 + u] = csum[u];
    __syncthreads();
    if (tid < 128) {
        float s = 0.f;
        #pragma unroll
        for (int q = 0; q < 16; ++q) s += red[q * 128 + tid];
        g_psum[blockIdx.x * HID + cb * 128 + tid] = s;
    }
    __syncthreads();
    #pragma unroll
    for (int u = 0; u < 8; ++u) red[tr * 128 + tc * 8 + u] = csq[u];
    __syncthreads();
    if (tid < 128) {
        float s = 0.f;
        #pragma unroll
        for (int q = 0; q < 16; ++q) s += red[q * 128 + tid];
        g_psq[blockIdx.x * HID + cb * 128 + tid] = s;
    }
}

// =====================================================================
// K2: finalize BN stats -> scale/shift
// =====================================================================
__global__ void k2_bnstats(const float* __restrict__ gamma,
                           const float* __restrict__ beta)
{
    __shared__ float rs[256], rq[256];
    const int c = blockIdx.x, tid = threadIdx.x;
    float s = 0.f, q = 0.f;
    for (int i = tid; i < GRID1; i += 256) {
        s += g_psum[i * HID + c];
        q += g_psq [i * HID + c];
    }
    rs[tid] = s; rq[tid] = q;
    __syncthreads();
    for (int off = 128; off > 0; off >>= 1) {
        if (tid < off) { rs[tid] += rs[tid + off]; rq[tid] += rq[tid + off]; }
        __syncthreads();
    }
    if (tid == 0) {
        const float invB = 1.f / (float)BATCH;
        float mu  = rs[0] * invB;
        float var = fmaxf(rq[0] * invB - mu * mu, 0.f);
        float sc  = gamma[c] * rsqrtf(var + 1e-5f);
        g_scale[c] = sc;
        g_shift[c] = beta[c] - mu * sc;
    }
}

// =====================================================================
// K3: enc = tanh( BN(h) @ W2 + b2 ). 128x128 tile, K=256 in chunks of 64.
// smem: A pairs [64][65]u64 | W2 chunk [64][128] | scale/shift/b2
// =====================================================================
#define K3_SMEM (64*65*8 + 64*128*4 + 256*4*2 + 128*4)  // 33280+32768+2048+512

__global__ void __launch_bounds__(256) k3_gemm_tanh(
    const float* __restrict__ W2, const float* __restrict__ b2)
{
    extern __shared__ char sm[];
    u64*   hA2 = (u64*)sm;                   // [kk][65]
    float* hAf = (float*)sm;                 // kk*130 + r
    float* wB  = (float*)(sm + 33280);       // [64][128]
    float* ssc = (float*)(sm + 66048);
    float* ssh = ssc + 256;
    float* sb2 = ssh + 256;

    const int tid  = threadIdx.x;
    const int row0 = blockIdx.x * 128;
    ssc[tid] = g_scale[tid];
    ssh[tid] = g_shift[tid];
    if (tid < 128) sb2[tid] = b2[tid];

    const int tc = tid & 15, tr = tid >> 4;
    u64 acc[4][8];
    #pragma unroll
    for (int j = 0; j < 4; ++j)
        #pragma unroll
        for (int u = 0; u < 8; ++u) acc[j][u] = 0ull;

    for (int kc = 0; kc < HID; kc += 64) {
        __syncthreads();
        for (int idx = tid; idx < 128 * 64; idx += 256) {
            int r = idx >> 6, kk = idx & 63;
            float v = g_h[(size_t)(row0 + r) * HID + kc + kk];
            hAf[kk * 130 + r] = v * ssc[kc + kk] + ssh[kc + kk];
        }
        for (int idx = tid; idx < 64 * 128; idx += 256)
            wB[idx] = W2[(size_t)(kc + (idx >> 7)) * ENC + (idx & 127)];
        __syncthreads();

        #pragma unroll 2
        for (int kk = 0; kk < 64; ++kk) {
            u64 p0 = hA2[kk * 65 + tr * 4 + 0];
            u64 p1 = hA2[kk * 65 + tr * 4 + 1];
            u64 p2 = hA2[kk * 65 + tr * 4 + 2];
            u64 p3 = hA2[kk * 65 + tr * 4 + 3];
            float4 wa = *(const float4*)(wB + kk * 128 + tc * 8);
            float4 wb = *(const float4*)(wB + kk * 128 + tc * 8 + 4);
            float wv[8] = {wa.x, wa.y, wa.z, wa.w, wb.x, wb.y, wb.z, wb.w};
            #pragma unroll
            for (int u = 0; u < 8; ++u) {
                u64 d = dupf(wv[u]);
                fma2(acc[0][u], p0, d); fma2(acc[1][u], p1, d);
                fma2(acc[2][u], p2, d); fma2(acc[3][u], p3, d);
            }
        }
    }

    #pragma unroll
    for (int j = 0; j < 4; ++j) {
        float v0[8], v1[8];
        #pragma unroll
        for (int u = 0; u < 8; ++u) {
            float2 t = unp(acc[j][u]);
            float bb = sb2[tc * 8 + u];
            v0[u] = ftanh(t.x + bb);
            v1[u] = ftanh(t.y + bb);
        }
        int rg = row0 + tr * 8 + 2 * j;
        float* ep = g_enc + (size_t)rg * ENC + tc * 8;
        *(float4*)ep       = make_float4(v0[0], v0[1], v0[2], v0[3]);
        *(float4*)(ep + 4) = make_float4(v0[4], v0[5], v0[6], v0[7]);
        ep += ENC;
        *(float4*)ep       = make_float4(v1[0], v1[1], v1[2], v1[3]);
        *(float4*)(ep + 4) = make_float4(v1[4], v1[5], v1[6], v1[7]);
    }
}

// =====================================================================
// K4: fused distance->softmax + 10 experts + weighted output.
// smem: enc pairs [128e][65rp]u64 | eh [128][69] | We1 [128][64] |
//       We2 padded [64][12] | att [10][128] | be1/be2/attn
// =====================================================================
#define K4_SMEM (128*65*8 + 128*69*4 + 128*64*4 + (768+1280+64+16+16)*4)

__global__ void __launch_bounds__(256) k4_fused(
    const float* __restrict__ We1, const float* __restrict__ be1,
    const float* __restrict__ We2, const float* __restrict__ be2,
    const float* __restrict__ attr, float* __restrict__ out)
{
    extern __shared__ char sm[];
    u64*   enc2 = (u64*)sm;                  // e*65 + rp
    float* encf = (float*)sm;                // e*130 + r
    float* ehs  = (float*)(sm + 66560);      // [128][69]
    float* we1s = (float*)(sm + 101888);     // [128][64]
    float* we2s = (float*)(sm + 134656);     // [64][12] padded
    float* att  = we2s + 768;                // [10][128]
    float* be1s = att + 1280;                // 64
    float* be2s = be1s + 64;                 // 16
    float* attn = be2s + 16;                 // 16

    const int tid  = threadIdx.x;
    const int row0 = blockIdx.x * 128;

    for (int idx = tid; idx < 128 * 128; idx += 256) {
        int r = idx >> 7, e = idx & 127;
        encf[e * 130 + r] = g_enc[(size_t)(row0 + r) * ENC + e];
    }
    for (int idx = tid; idx < NK * ENC; idx += 256) att[idx] = attr[idx];
    __syncthreads();
    if (tid < NK) {
        float s = 0.f;
        for (int e = 0; e < ENC; ++e) { float v = att[tid * ENC + e]; s += v * v; }
        attn[tid] = s;
    }
    __syncthreads();

    // distances + softmax -> strengths in registers (threads 0..127 own a row)
    float strk[NK];
    float outacc[ACTD];
    #pragma unroll
    for (int a = 0; a < ACTD; ++a) outacc[a] = 0.f;

    if (tid < 128) {
        float en = 0.f;
        for (int e = 0; e < ENC; ++e) { float v = encf[e * 130 + tid]; en += v * v; }
        float mx = -1e30f;
        #pragma unroll
        for (int k = 0; k < NK; ++k) {
            float d = 0.f;
            for (int e = 0; e < ENC; ++e) d += encf[e * 130 + tid] * att[k * ENC + e];
            float d2 = fmaxf(en + attn[k] - 2.f * d, 0.f);
            strk[k] = -2.f * sqrtf(d2);          // -dist/TEMP, TEMP=0.5
            mx = fmaxf(mx, strk[k]);
        }
        float s = 0.f;
        #pragma unroll
        for (int k = 0; k < NK; ++k) { strk[k] = __expf(strk[k] - mx); s += strk[k]; }
        float inv = __fdividef(1.f, s);
        #pragma unroll
        for (int k = 0; k < NK; ++k) strk[k] *= inv;
    }

    const int tc = tid & 15, trr = tid >> 4;
    for (int k = 0; k < NK; ++k) {
        __syncthreads();
        for (int idx = tid; idx < ENC * EXPH; idx += 256)
            we1s[idx] = We1[(size_t)k * ENC * EXPH + idx];
        for (int idx = tid; idx < EXPH * ACTD; idx += 256)
            we2s[(idx / ACTD) * 12 + (idx % ACTD)] = We2[k * EXPH * ACTD + idx];
        if (tid < EXPH) be1s[tid] = be1[k * EXPH + tid];
        if (tid < ACTD) be2s[tid] = be2[k * ACTD + tid];
        __syncthreads();

        // phase A: eh = relu(enc @ We1_k + be1_k), 8 rows x 4 cols / thread
        u64 acc[4][4];
        #pragma unroll
        for (int j = 0; j < 4; ++j)
            #pragma unroll
            for (int u = 0; u < 4; ++u) acc[j][u] = 0ull;

        #pragma unroll 2
        for (int e = 0; e < ENC; ++e) {
            u64 p0 = enc2[e * 65 + trr * 4 + 0];
            u64 p1 = enc2[e * 65 + trr * 4 + 1];
            u64 p2 = enc2[e * 65 + trr * 4 + 2];
            u64 p3 = enc2[e * 65 + trr * 4 + 3];
            float4 w = *(const float4*)(we1s + e * 64 + tc * 4);
            float wv[4] = {w.x, w.y, w.z, w.w};
            #pragma unroll
            for (int u = 0; u < 4; ++u) {
                u64 d = dupf(wv[u]);
                fma2(acc[0][u], p0, d); fma2(acc[1][u], p1, d);
                fma2(acc[2][u], p2, d); fma2(acc[3][u], p3, d);
            }
        }
        #pragma unroll
        for (int j = 0; j < 4; ++j) {
            int r = trr * 8 + 2 * j;
            #pragma unroll
            for (int u = 0; u < 4; ++u) {
                float2 t = unp(acc[j][u]);
                float bb = be1s[tc * 4 + u];
                ehs[r * 69 + tc * 4 + u]       = fmaxf(t.x + bb, 0.f);
                ehs[(r + 1) * 69 + tc * 4 + u] = fmaxf(t.y + bb, 0.f);
            }
        }
        __syncthreads();

        // phase B: out += s_k * (eh @ We2_k + be2_k), threads 0..127 own rows
        if (tid < 128) {
            float o[ACTD];
            #pragma unroll
            for (int a = 0; a < ACTD; ++a) o[a] = 0.f;
            #pragma unroll 4
            for (int h = 0; h < EXPH; ++h) {
                float ev = ehs[tid * 69 + h];
                float4 wa = *(const float4*)(we2s + h * 12);
                float4 wb = *(const float4*)(we2s + h * 12 + 4);
                float4 wc = *(const float4*)(we2s + h * 12 + 8);
                o[0] += ev * wa.x; o[1] += ev * wa.y; o[2] += ev * wa.z; o[3] += ev * wa.w;
                o[4] += ev * wb.x; o[5] += ev * wb.y; o[6] += ev * wb.z; o[7] += ev * wb.w;
                o[8] += ev * wc.x; o[9] += ev * wc.y;
            }
            float s = strk[k];
            #pragma unroll
            for (int a = 0; a < ACTD; ++a) outacc[a] += s * (o[a] + be2s[a]);
        }
    }

    if (tid < 128) {
        float* op = out + (size_t)(row0 + tid) * ACTD;
        #pragma unroll
        for (int a = 0; a < ACTD; ++a) op[a] = outacc[a];
    }
}

// =====================================================================
extern "C" void kernel_launch(void* const* d_in, const int* in_sizes, int n_in,
                              void* d_out, int out_size)
{
    const float* state = (const float*)d_in[0];
    const float* W1    = (const float*)d_in[1];
    const float* b1    = (const float*)d_in[2];
    const float* gamma = (const float*)d_in[3];
    const float* beta  = (const float*)d_in[4];
    const float* W2    = (const float*)d_in[5];
    const float* b2    = (const float*)d_in[6];
    const float* We1   = (const float*)d_in[7];
    const float* be1   = (const float*)d_in[8];
    const float* We2   = (const float*)d_in[9];
    const float* be2   = (const float*)d_in[10];
    const float* attr  = (const float*)d_in[11];
    float* out = (float*)d_out;

    cudaFuncSetAttribute(k1_gemm_relu, cudaFuncAttributeMaxDynamicSharedMemorySize, K1_SMEM);
    cudaFuncSetAttribute(k3_gemm_tanh, cudaFuncAttributeMaxDynamicSharedMemorySize, K3_SMEM);
    cudaFuncSetAttribute(k4_fused,     cudaFuncAttributeMaxDynamicSharedMemorySize, K4_SMEM);

    k1_gemm_relu<<<dim3(GRID1, 2), 256, K1_SMEM>>>(state, W1, b1);
    k2_bnstats<<<HID, 256>>>(gamma, beta);
    k3_gemm_tanh<<<GRID1, 256, K3_SMEM>>>(W2, b2);
    k4_fused<<<GRID1, 256, K4_SMEM>>>(We1, be1, We2, be2, attr, out);
}

// round 14
// speedup vs baseline: 1.5068x; 1.5068x over previous
#include <cuda_runtime.h>

#define BATCH 262144
#define SDIM  100
#define HID   256
#define ENC   128
#define EXPH  64
#define ACTD  10
#define NK    10
#define GRID1 2048          // BATCH/128

typedef unsigned long long u64;

// ---- device-global scratch (no allocation allowed) ----
__device__ float g_h[BATCH * HID];
__device__ float g_enc[BATCH * ENC];
__device__ float g_psum[GRID1 * HID];
__device__ float g_psq [GRID1 * HID];
__device__ float g_scale[HID];
__device__ float g_shift[HID];

// ---- packed fp32x2 helpers (FFMA2 only reachable via PTX) ----
__device__ __forceinline__ u64 dupf(float w) {
    u64 d; asm("mov.b64 %0, {%1, %1};" : "=l"(d) : "f"(w)); return d;
}
__device__ __forceinline__ u64 pack2(float a, float b) {
    u64 d; asm("mov.b64 %0, {%1, %2};" : "=l"(d) : "f"(a), "f"(b)); return d;
}
__device__ __forceinline__ void fma2(u64 &a, u64 x, u64 y) {
    asm("fma.rn.f32x2 %0, %1, %2, %0;" : "+l"(a) : "l"(x), "l"(y));
}
__device__ __forceinline__ float2 unp(u64 v) {
    float2 r; asm("mov.b64 {%0, %1}, %2;" : "=f"(r.x), "=f"(r.y) : "l"(v)); return r;
}
__device__ __forceinline__ float ftanh(float x) {
    float v = fminf(fmaxf(x, -15.f), 15.f);
    float t = __expf(2.f * v);
    return __fdividef(t - 1.f, t + 1.f);
}

// =====================================================================
// K1: h = relu(state @ W1 + b1) + per-block column sum/sumsq
// 512 threads, tile 128 rows x 128 cols, per-thread 8r x 4c.
// smem: st pairs [100][65]u64 | W1 [100][128] | b1   = 103712 B, 2 CTA/SM
// =====================================================================
#define K1_SMEM (100*65*8 + 100*128*4 + 128*4)   // 52000+51200+512

__global__ void __launch_bounds__(512, 2) k1_gemm_relu(
    const float* __restrict__ state, const float* __restrict__ W1,
    const float* __restrict__ b1)
{
    extern __shared__ char sm[];
    float* stf = (float*)sm;                 // float view: k*130 + r
    u64*   st2 = (u64*)sm;                   // pair view:  k*65 + rp
    float* w1s = (float*)(sm + 52000);       // [100][128]
    float* b1s = (float*)(sm + 103200);

    const int tid  = threadIdx.x;
    const int row0 = blockIdx.x * 128;
    const int cb   = blockIdx.y;

    for (int idx = tid; idx < 128 * SDIM; idx += 512) {
        int r = idx / SDIM, k = idx - r * SDIM;
        stf[k * 130 + r] = state[(size_t)(row0 + r) * SDIM + k];
    }
    for (int idx = tid; idx < SDIM * 128; idx += 512) {
        int k = idx >> 7, c = idx & 127;
        w1s[idx] = W1[k * HID + cb * 128 + c];
    }
    if (tid < 128) b1s[tid] = b1[cb * 128 + tid];
    __syncthreads();

    const int tc = tid & 31, tr = tid >> 5;  // 32 col-groups x 16 row-groups
    u64 acc[4][4];
    #pragma unroll
    for (int j = 0; j < 4; ++j)
        #pragma unroll
        for (int u = 0; u < 4; ++u) acc[j][u] = 0ull;

    #pragma unroll 2
    for (int k = 0; k < SDIM; ++k) {
        u64 p0 = st2[k * 65 + tr * 4 + 0];
        u64 p1 = st2[k * 65 + tr * 4 + 1];
        u64 p2 = st2[k * 65 + tr * 4 + 2];
        u64 p3 = st2[k * 65 + tr * 4 + 3];
        float4 w = *(const float4*)(w1s + k * 128 + tc * 4);
        float wv[4] = {w.x, w.y, w.z, w.w};
        #pragma unroll
        for (int u = 0; u < 4; ++u) {
            u64 d = dupf(wv[u]);
            fma2(acc[0][u], p0, d); fma2(acc[1][u], p1, d);
            fma2(acc[2][u], p2, d); fma2(acc[3][u], p3, d);
        }
    }

    float csum[4], csq[4], bvals[4];
    #pragma unroll
    for (int u = 0; u < 4; ++u) { csum[u] = 0.f; csq[u] = 0.f; bvals[u] = b1s[tc * 4 + u]; }

    #pragma unroll
    for (int j = 0; j < 4; ++j) {
        float v0[4], v1[4];
        #pragma unroll
        for (int u = 0; u < 4; ++u) {
            float2 t = unp(acc[j][u]);
            float x0 = fmaxf(t.x + bvals[u], 0.f);
            float x1 = fmaxf(t.y + bvals[u], 0.f);
            v0[u] = x0; v1[u] = x1;
            csum[u] += x0 + x1;
            csq[u]  += x0 * x0 + x1 * x1;
        }
        int rg = row0 + tr * 8 + 2 * j;
        float* hp = g_h + (size_t)rg * HID + cb * 128 + tc * 4;
        *(float4*)hp = make_float4(v0[0], v0[1], v0[2], v0[3]);
        hp += HID;
        *(float4*)hp = make_float4(v1[0], v1[1], v1[2], v1[3]);
    }

    __syncthreads();
    float* red = (float*)sm;                 // alias, [16][128]
    #pragma unroll
    for (int u = 0; u < 4; ++u) red[tr * 128 + tc * 4 + u] = csum[u];
    __syncthreads();
    if (tid < 128) {
        float s = 0.f;
        #pragma unroll
        for (int q = 0; q < 16; ++q) s += red[q * 128 + tid];
        g_psum[blockIdx.x * HID + cb * 128 + tid] = s;
    }
    __syncthreads();
    #pragma unroll
    for (int u = 0; u < 4; ++u) red[tr * 128 + tc * 4 + u] = csq[u];
    __syncthreads();
    if (tid < 128) {
        float s = 0.f;
        #pragma unroll
        for (int q = 0; q < 16; ++q) s += red[q * 128 + tid];
        g_psq[blockIdx.x * HID + cb * 128 + tid] = s;
    }
}

// =====================================================================
// K2: finalize BN stats -> scale/shift
// =====================================================================
__global__ void k2_bnstats(const float* __restrict__ gamma,
                           const float* __restrict__ beta)
{
    __shared__ float rs[256], rq[256];
    const int c = blockIdx.x, tid = threadIdx.x;
    float s = 0.f, q = 0.f;
    for (int i = tid; i < GRID1; i += 256) {
        s += g_psum[i * HID + c];
        q += g_psq [i * HID + c];
    }
    rs[tid] = s; rq[tid] = q;
    __syncthreads();
    for (int off = 128; off > 0; off >>= 1) {
        if (tid < off) { rs[tid] += rs[tid + off]; rq[tid] += rq[tid + off]; }
        __syncthreads();
    }
    if (tid == 0) {
        const float invB = 1.f / (float)BATCH;
        float mu  = rs[0] * invB;
        float var = fmaxf(rq[0] * invB - mu * mu, 0.f);
        float sc  = gamma[c] * rsqrtf(var + 1e-5f);
        g_scale[c] = sc;
        g_shift[c] = beta[c] - mu * sc;
    }
}

// =====================================================================
// K3: enc = tanh( BN(h) @ W2 + b2 ). 512 threads, 128x128 tile,
// K=256 in chunks of 64, per-thread 8r x 4c. smem 68608 B, 2 CTA/SM.
// =====================================================================
#define K3_SMEM (64*65*8 + 64*128*4 + 256*4*2 + 128*4)  // 33280+32768+2048+512

__global__ void __launch_bounds__(512, 2) k3_gemm_tanh(
    const float* __restrict__ W2, const float* __restrict__ b2)
{
    extern __shared__ char sm[];
    u64*   hA2 = (u64*)sm;                   // [kk][65]
    float* hAf = (float*)sm;                 // kk*130 + r
    float* wB  = (float*)(sm + 33280);       // [64][128]
    float* ssc = (float*)(sm + 66048);
    float* ssh = ssc + 256;
    float* sb2 = ssh + 256;

    const int tid  = threadIdx.x;
    const int row0 = blockIdx.x * 128;
    if (tid < 256) { ssc[tid] = g_scale[tid]; ssh[tid] = g_shift[tid]; }
    if (tid < 128) sb2[tid] = b2[tid];

    const int tc = tid & 31, tr = tid >> 5;
    u64 acc[4][4];
    #pragma unroll
    for (int j = 0; j < 4; ++j)
        #pragma unroll
        for (int u = 0; u < 4; ++u) acc[j][u] = 0ull;

    for (int kc = 0; kc < HID; kc += 64) {
        __syncthreads();
        for (int idx = tid; idx < 128 * 64; idx += 512) {
            int r = idx >> 6, kk = idx & 63;
            float v = g_h[(size_t)(row0 + r) * HID + kc + kk];
            hAf[kk * 130 + r] = v * ssc[kc + kk] + ssh[kc + kk];
        }
        for (int idx = tid; idx < 64 * 128; idx += 512)
            wB[idx] = W2[(size_t)(kc + (idx >> 7)) * ENC + (idx & 127)];
        __syncthreads();

        #pragma unroll 2
        for (int kk = 0; kk < 64; ++kk) {
            u64 p0 = hA2[kk * 65 + tr * 4 + 0];
            u64 p1 = hA2[kk * 65 + tr * 4 + 1];
            u64 p2 = hA2[kk * 65 + tr * 4 + 2];
            u64 p3 = hA2[kk * 65 + tr * 4 + 3];
            float4 w = *(const float4*)(wB + kk * 128 + tc * 4);
            float wv[4] = {w.x, w.y, w.z, w.w};
            #pragma unroll
            for (int u = 0; u < 4; ++u) {
                u64 d = dupf(wv[u]);
                fma2(acc[0][u], p0, d); fma2(acc[1][u], p1, d);
                fma2(acc[2][u], p2, d); fma2(acc[3][u], p3, d);
            }
        }
    }

    #pragma unroll
    for (int j = 0; j < 4; ++j) {
        float v0[4], v1[4];
        #pragma unroll
        for (int u = 0; u < 4; ++u) {
            float2 t = unp(acc[j][u]);
            float bb = sb2[tc * 4 + u];
            v0[u] = ftanh(t.x + bb);
            v1[u] = ftanh(t.y + bb);
        }
        int rg = row0 + tr * 8 + 2 * j;
        float* ep = g_enc + (size_t)rg * ENC + tc * 4;
        *(float4*)ep = make_float4(v0[0], v0[1], v0[2], v0[3]);
        ep += ENC;
        *(float4*)ep = make_float4(v1[0], v1[1], v1[2], v1[3]);
    }
}

// =====================================================================
// K4: fused distance->softmax + 10 experts + weighted output.
// 256 threads. smem layout (110144 B total -> 2 CTA/SM):
//   [0, 66560)       enc pairs [128e][65rp] u64  (float view pitch 130)
//   [66560, 99840)   X: we1 [128][64] f  OR  ehT pairs [64h][65rp] u64
//   [99840, 104960)  Y: att [10][128]  ->  we2s [64][12] | be1s | be2s
//   [104960, 110080) sstr [10][128]
//   [110080, 110144) attn [16]
// =====================================================================
#define K4_SMEM 110144

__global__ void __launch_bounds__(256) k4_fused(
    const float* __restrict__ We1, const float* __restrict__ be1,
    const float* __restrict__ We2, const float* __restrict__ be2,
    const float* __restrict__ attr, float* __restrict__ out)
{
    extern __shared__ char sm[];
    u64*   enc2 = (u64*)sm;                  // e*65 + rp
    float* encf = (float*)sm;                // e*130 + r
    float* Xf   = (float*)(sm + 66560);      // we1 view / ehT float view (h*130+r)
    u64*   X2   = (u64*)(sm + 66560);        // ehT pair view (h*65+rp)
    float* att  = (float*)(sm + 99840);      // [10][128] during distance phase
    float* we2s = att;                        // [64][12] after
    float* be1s = (float*)(sm + 99840 + 3072);
    float* be2s = (float*)(sm + 99840 + 3328);
    float* sstr = (float*)(sm + 104960);     // [10][128]
    float* attn = (float*)(sm + 110080);

    const int tid  = threadIdx.x;
    const int row0 = blockIdx.x * 128;
    const int r    = tid & 127, half = tid >> 7;

    for (int idx = tid; idx < 128 * 128; idx += 256) {
        int rr = idx >> 7, e = idx & 127;
        encf[e * 130 + rr] = g_enc[(size_t)(row0 + rr) * ENC + e];
    }
    for (int idx = tid; idx < NK * ENC; idx += 256) att[idx] = attr[idx];
    __syncthreads();
    if (tid < NK) {
        float s = 0.f;
        for (int e = 0; e < ENC; ++e) { float v = att[tid * ENC + e]; s += v * v; }
        attn[tid] = s;
    }
    __syncthreads();

    // distances: all 256 threads, 5 experts per half
    {
        float en = 0.f, dk[5] = {0.f, 0.f, 0.f, 0.f, 0.f};
        const float* ap = att + half * 5 * ENC;
        for (int e = 0; e < ENC; ++e) {
            float v = encf[e * 130 + r];
            en += v * v;
            #pragma unroll
            for (int q = 0; q < 5; ++q) dk[q] += v * ap[q * ENC + e];
        }
        #pragma unroll
        for (int q = 0; q < 5; ++q) {
            int k = half * 5 + q;
            float d2 = fmaxf(en + attn[k] - 2.f * dk[q], 0.f);
            sstr[k * 128 + r] = -2.f * sqrtf(d2);     // -dist/TEMP, TEMP=0.5
        }
    }
    __syncthreads();
    if (tid < 128) {
        float v[NK], mx = -1e30f;
        #pragma unroll
        for (int k = 0; k < NK; ++k) { v[k] = sstr[k * 128 + tid]; mx = fmaxf(mx, v[k]); }
        float s = 0.f;
        #pragma unroll
        for (int k = 0; k < NK; ++k) { v[k] = __expf(v[k] - mx); s += v[k]; }
        float inv = __fdividef(1.f, s);
        #pragma unroll
        for (int k = 0; k < NK; ++k) sstr[k * 128 + tid] = v[k] * inv;
    }
    __syncthreads();

    // preload we1_0 + be1_0 (att region is now dead -> Y becomes we2/be1/be2)
    for (int idx = tid; idx < ENC * EXPH; idx += 256) Xf[idx] = We1[idx];
    if (tid < EXPH) be1s[tid] = be1[tid];
    __syncthreads();

    const int tc = tid & 15, trr = tid >> 4;
    float outacc[ACTD];
    #pragma unroll
    for (int a = 0; a < ACTD; ++a) outacc[a] = 0.f;

    for (int k = 0; k < NK; ++k) {
        // phase A: eh = relu(enc @ We1_k + be1_k), 8 rows x 4 cols / thread
        u64 acc[4][4];
        #pragma unroll
        for (int j = 0; j < 4; ++j)
            #pragma unroll
            for (int u = 0; u < 4; ++u) acc[j][u] = 0ull;

        #pragma unroll 2
        for (int e = 0; e < ENC; ++e) {
            u64 p0 = enc2[e * 65 + trr * 4 + 0];
            u64 p1 = enc2[e * 65 + trr * 4 + 1];
            u64 p2 = enc2[e * 65 + trr * 4 + 2];
            u64 p3 = enc2[e * 65 + trr * 4 + 3];
            float4 w = *(const float4*)(Xf + e * 64 + tc * 4);
            float wv[4] = {w.x, w.y, w.z, w.w};
            #pragma unroll
            for (int u = 0; u < 4; ++u) {
                u64 d = dupf(wv[u]);
                fma2(acc[0][u], p0, d); fma2(acc[1][u], p1, d);
                fma2(acc[2][u], p2, d); fma2(acc[3][u], p3, d);
            }
        }
        __syncthreads();   // (1) all done reading X(we1)

        // write ehT (transposed, packed row pairs) into X; stage we2/be2
        #pragma unroll
        for (int u = 0; u < 4; ++u) {
            float bb = be1s[tc * 4 + u];
            #pragma unroll
            for (int j = 0; j < 4; ++j) {
                float2 t = unp(acc[j][u]);
                float x0 = fmaxf(t.x + bb, 0.f);
                float x1 = fmaxf(t.y + bb, 0.f);
                X2[(tc * 4 + u) * 65 + trr * 4 + j] = pack2(x0, x1);
            }
        }
        for (int idx = tid; idx < EXPH * ACTD; idx += 256)
            we2s[(idx / ACTD) * 12 + (idx % ACTD)] = We2[k * EXPH * ACTD + idx];
        if (tid < ACTD) be2s[tid] = be2[k * ACTD + tid];
        __syncthreads();   // (2) eh + we2 visible

        // phase B: all 256 threads, h split across halves
        {
            float o[ACTD];
            #pragma unroll
            for (int a = 0; a < ACTD; ++a) o[a] = 0.f;
            const int hb = half * 32;
            #pragma unroll 4
            for (int h = 0; h < 32; ++h) {
                float ev = Xf[(hb + h) * 130 + r];
                const float* wp = we2s + (hb + h) * 12;
                float4 wa = *(const float4*)(wp);
                float4 wb = *(const float4*)(wp + 4);
                float4 wc = *(const float4*)(wp + 8);
                o[0] += ev * wa.x; o[1] += ev * wa.y; o[2] += ev * wa.z; o[3] += ev * wa.w;
                o[4] += ev * wb.x; o[5] += ev * wb.y; o[6] += ev * wb.z; o[7] += ev * wb.w;
                o[8] += ev * wc.x; o[9] += ev * wc.y;
            }
            float s = sstr[k * 128 + r];
            if (half == 0) {
                #pragma unroll
                for (int a = 0; a < ACTD; ++a) outacc[a] += s * (o[a] + be2s[a]);
            } else {
                #pragma unroll
                for (int a = 0; a < ACTD; ++a) outacc[a] += s * o[a];
            }
        }
        __syncthreads();   // (3) done reading X(eh) + we2

        if (k + 1 < NK) {
            for (int idx = tid; idx < ENC * EXPH; idx += 256)
                Xf[idx] = We1[(size_t)(k + 1) * ENC * EXPH + idx];
            if (tid < EXPH) be1s[tid] = be1[(k + 1) * EXPH + tid];
        }
        __syncthreads();   // (4) next we1 ready
    }

    // combine halves via X region (dead now) and write output
    if (half == 1) {
        #pragma unroll
        for (int a = 0; a < ACTD; ++a) Xf[r * 12 + a] = outacc[a];
    }
    __syncthreads();
    if (half == 0) {
        float* op = out + (size_t)(row0 + r) * ACTD;
        #pragma unroll
        for (int a = 0; a < ACTD; ++a) op[a] = outacc[a] + Xf[r * 12 + a];
    }
}

// =====================================================================
extern "C" void kernel_launch(void* const* d_in, const int* in_sizes, int n_in,
                              void* d_out, int out_size)
{
    const float* state = (const float*)d_in[0];
    const float* W1    = (const float*)d_in[1];
    const float* b1    = (const float*)d_in[2];
    const float* gamma = (const float*)d_in[3];
    const float* beta  = (const float*)d_in[4];
    const float* W2    = (const float*)d_in[5];
    const float* b2    = (const float*)d_in[6];
    const float* We1   = (const float*)d_in[7];
    const float* be1   = (const float*)d_in[8];
    const float* We2   = (const float*)d_in[9];
    const float* be2   = (const float*)d_in[10];
    const float* attr  = (const float*)d_in[11];
    float* out = (float*)d_out;

    cudaFuncSetAttribute(k1_gemm_relu, cudaFuncAttributeMaxDynamicSharedMemorySize, K1_SMEM);
    cudaFuncSetAttribute(k3_gemm_tanh, cudaFuncAttributeMaxDynamicSharedMemorySize, K3_SMEM);
    cudaFuncSetAttribute(k4_fused,     cudaFuncAttributeMaxDynamicSharedMemorySize, K4_SMEM);

    k1_gemm_relu<<<dim3(GRID1, 2), 512, K1_SMEM>>>(state, W1, b1);
    k2_bnstats<<<HID, 256>>>(gamma, beta);
    k3_gemm_tanh<<<GRID1, 512, K3_SMEM>>>(W2, b2);
    k4_fused<<<GRID1, 256, K4_SMEM>>>(We1, be1, We2, be2, attr, out);
}

// round 17
// speedup vs baseline: 1.6250x; 1.0784x over previous
#include <cuda_runtime.h>
#include <cuda_bf16.h>
#include <cstdint>

#define BATCH 262144
#define SDIM  100
#define HID   256
#define ENC   128
#define EXPH  64
#define ACTD  10
#define NK    10
#define GRID1 2048          // BATCH/128

typedef unsigned long long u64;
typedef unsigned int u32;

// ---- device-global scratch (no allocation allowed) ----
__device__ float g_h[BATCH * HID];
__device__ float g_enc[BATCH * ENC];
__device__ float g_psum[GRID1 * HID];
__device__ float g_psq [GRID1 * HID];
__device__ float g_scale[HID];
__device__ float g_shift[HID];

// ---- packed fp32x2 helpers (FFMA2 only reachable via PTX) ----
__device__ __forceinline__ u64 dupf(float w) {
    u64 d; asm("mov.b64 %0, {%1, %1};" : "=l"(d) : "f"(w)); return d;
}
__device__ __forceinline__ void fma2(u64 &a, u64 x, u64 y) {
    asm("fma.rn.f32x2 %0, %1, %2, %0;" : "+l"(a) : "l"(x), "l"(y));
}
__device__ __forceinline__ float2 unp(u64 v) {
    float2 r; asm("mov.b64 {%0, %1}, %2;" : "=f"(r.x), "=f"(r.y) : "l"(v)); return r;
}
__device__ __forceinline__ float ftanh(float x) {
    float v = fminf(fmaxf(x, -15.f), 15.f);
    float t = __expf(2.f * v);
    return __fdividef(t - 1.f, t + 1.f);
}

// ---- bf16 split helper: two floats -> packed bf16x2 hi + lo residual ----
__device__ __forceinline__ void split2(float v0, float v1, u32 &hi, u32 &lo) {
    __nv_bfloat16 h0 = __float2bfloat16(v0), h1 = __float2bfloat16(v1);
    float r0 = v0 - __bfloat162float(h0);
    float r1 = v1 - __bfloat162float(h1);
    __nv_bfloat16 l0 = __float2bfloat16(r0), l1 = __float2bfloat16(r1);
    hi = (u32)__bfloat16_as_ushort(h0) | ((u32)__bfloat16_as_ushort(h1) << 16);
    lo = (u32)__bfloat16_as_ushort(l0) | ((u32)__bfloat16_as_ushort(l1) << 16);
}

// ---- m16n8k16 bf16 HMMA (baseline PTX; legal on compute_103) ----
__device__ __forceinline__ void mma_bf16(float (&d)[4], u32 a0, u32 a1, u32 a2, u32 a3,
                                         u32 b0, u32 b1) {
    asm volatile(
        "mma.sync.aligned.m16n8k16.row.col.f32.bf16.bf16.f32 "
        "{%0,%1,%2,%3}, {%4,%5,%6,%7}, {%8,%9}, {%0,%1,%2,%3};"
        : "+f"(d[0]), "+f"(d[1]), "+f"(d[2]), "+f"(d[3])
        : "r"(a0), "r"(a1), "r"(a2), "r"(a3), "r"(b0), "r"(b1));
}

// =====================================================================
// K1: h = relu(state @ W1 + b1) + per-block column sum/sumsq
// =====================================================================
#define K1_SMEM (100*65*8 + 100*128*4 + 128*4)

__global__ void __launch_bounds__(512, 2) k1_gemm_relu(
    const float* __restrict__ state, const float* __restrict__ W1,
    const float* __restrict__ b1)
{
    extern __shared__ char sm[];
    float* stf = (float*)sm;
    u64*   st2 = (u64*)sm;
    float* w1s = (float*)(sm + 52000);
    float* b1s = (float*)(sm + 103200);

    const int tid  = threadIdx.x;
    const int row0 = blockIdx.x * 128;
    const int cb   = blockIdx.y;

    for (int idx = tid; idx < 128 * SDIM; idx += 512) {
        int r = idx / SDIM, k = idx - r * SDIM;
        stf[k * 130 + r] = state[(size_t)(row0 + r) * SDIM + k];
    }
    for (int idx = tid; idx < SDIM * 128; idx += 512) {
        int k = idx >> 7, c = idx & 127;
        w1s[idx] = W1[k * HID + cb * 128 + c];
    }
    if (tid < 128) b1s[tid] = b1[cb * 128 + tid];
    __syncthreads();

    const int tc = tid & 31, tr = tid >> 5;
    u64 acc[4][4];
    #pragma unroll
    for (int j = 0; j < 4; ++j)
        #pragma unroll
        for (int u = 0; u < 4; ++u) acc[j][u] = 0ull;

    #pragma unroll 2
    for (int k = 0; k < SDIM; ++k) {
        u64 p0 = st2[k * 65 + tr * 4 + 0];
        u64 p1 = st2[k * 65 + tr * 4 + 1];
        u64 p2 = st2[k * 65 + tr * 4 + 2];
        u64 p3 = st2[k * 65 + tr * 4 + 3];
        float4 w = *(const float4*)(w1s + k * 128 + tc * 4);
        float wv[4] = {w.x, w.y, w.z, w.w};
        #pragma unroll
        for (int u = 0; u < 4; ++u) {
            u64 d = dupf(wv[u]);
            fma2(acc[0][u], p0, d); fma2(acc[1][u], p1, d);
            fma2(acc[2][u], p2, d); fma2(acc[3][u], p3, d);
        }
    }

    float csum[4], csq[4], bvals[4];
    #pragma unroll
    for (int u = 0; u < 4; ++u) { csum[u] = 0.f; csq[u] = 0.f; bvals[u] = b1s[tc * 4 + u]; }

    #pragma unroll
    for (int j = 0; j < 4; ++j) {
        float v0[4], v1[4];
        #pragma unroll
        for (int u = 0; u < 4; ++u) {
            float2 t = unp(acc[j][u]);
            float x0 = fmaxf(t.x + bvals[u], 0.f);
            float x1 = fmaxf(t.y + bvals[u], 0.f);
            v0[u] = x0; v1[u] = x1;
            csum[u] += x0 + x1;
            csq[u]  += x0 * x0 + x1 * x1;
        }
        int rg = row0 + tr * 8 + 2 * j;
        float* hp = g_h + (size_t)rg * HID + cb * 128 + tc * 4;
        *(float4*)hp = make_float4(v0[0], v0[1], v0[2], v0[3]);
        hp += HID;
        *(float4*)hp = make_float4(v1[0], v1[1], v1[2], v1[3]);
    }

    __syncthreads();
    float* red = (float*)sm;
    #pragma unroll
    for (int u = 0; u < 4; ++u) red[tr * 128 + tc * 4 + u] = csum[u];
    __syncthreads();
    if (tid < 128) {
        float s = 0.f;
        #pragma unroll
        for (int q = 0; q < 16; ++q) s += red[q * 128 + tid];
        g_psum[blockIdx.x * HID + cb * 128 + tid] = s;
    }
    __syncthreads();
    #pragma unroll
    for (int u = 0; u < 4; ++u) red[tr * 128 + tc * 4 + u] = csq[u];
    __syncthreads();
    if (tid < 128) {
        float s = 0.f;
        #pragma unroll
        for (int q = 0; q < 16; ++q) s += red[q * 128 + tid];
        g_psq[blockIdx.x * HID + cb * 128 + tid] = s;
    }
}

// =====================================================================
// K2: finalize BN stats -> scale/shift
// =====================================================================
__global__ void k2_bnstats(const float* __restrict__ gamma,
                           const float* __restrict__ beta)
{
    __shared__ float rs[256], rq[256];
    const int c = blockIdx.x, tid = threadIdx.x;
    float s = 0.f, q = 0.f;
    for (int i = tid; i < GRID1; i += 256) {
        s += g_psum[i * HID + c];
        q += g_psq [i * HID + c];
    }
    rs[tid] = s; rq[tid] = q;
    __syncthreads();
    for (int off = 128; off > 0; off >>= 1) {
        if (tid < off) { rs[tid] += rs[tid + off]; rq[tid] += rq[tid + off]; }
        __syncthreads();
    }
    if (tid == 0) {
        const float invB = 1.f / (float)BATCH;
        float mu  = rs[0] * invB;
        float var = fmaxf(rq[0] * invB - mu * mu, 0.f);
        float sc  = gamma[c] * rsqrtf(var + 1e-5f);
        g_scale[c] = sc;
        g_shift[c] = beta[c] - mu * sc;
    }
}

// =====================================================================
// K3: enc = tanh( BN(h) @ W2 + b2 )
// =====================================================================
#define K3_SMEM (64*65*8 + 64*128*4 + 256*4*2 + 128*4)

__global__ void __launch_bounds__(512, 2) k3_gemm_tanh(
    const float* __restrict__ W2, const float* __restrict__ b2)
{
    extern __shared__ char sm[];
    u64*   hA2 = (u64*)sm;
    float* hAf = (float*)sm;
    float* wB  = (float*)(sm + 33280);
    float* ssc = (float*)(sm + 66048);
    float* ssh = ssc + 256;
    float* sb2 = ssh + 256;

    const int tid  = threadIdx.x;
    const int row0 = blockIdx.x * 128;
    if (tid < 256) { ssc[tid] = g_scale[tid]; ssh[tid] = g_shift[tid]; }
    if (tid < 128) sb2[tid] = b2[tid];

    const int tc = tid & 31, tr = tid >> 5;
    u64 acc[4][4];
    #pragma unroll
    for (int j = 0; j < 4; ++j)
        #pragma unroll
        for (int u = 0; u < 4; ++u) acc[j][u] = 0ull;

    for (int kc = 0; kc < HID; kc += 64) {
        __syncthreads();
        for (int idx = tid; idx < 128 * 64; idx += 512) {
            int r = idx >> 6, kk = idx & 63;
            float v = g_h[(size_t)(row0 + r) * HID + kc + kk];
            hAf[kk * 130 + r] = v * ssc[kc + kk] + ssh[kc + kk];
        }
        for (int idx = tid; idx < 64 * 128; idx += 512)
            wB[idx] = W2[(size_t)(kc + (idx >> 7)) * ENC + (idx & 127)];
        __syncthreads();

        #pragma unroll 2
        for (int kk = 0; kk < 64; ++kk) {
            u64 p0 = hA2[kk * 65 + tr * 4 + 0];
            u64 p1 = hA2[kk * 65 + tr * 4 + 1];
            u64 p2 = hA2[kk * 65 + tr * 4 + 2];
            u64 p3 = hA2[kk * 65 + tr * 4 + 3];
            float4 w = *(const float4*)(wB + kk * 128 + tc * 4);
            float wv[4] = {w.x, w.y, w.z, w.w};
            #pragma unroll
            for (int u = 0; u < 4; ++u) {
                u64 d = dupf(wv[u]);
                fma2(acc[0][u], p0, d); fma2(acc[1][u], p1, d);
                fma2(acc[2][u], p2, d); fma2(acc[3][u], p3, d);
            }
        }
    }

    #pragma unroll
    for (int j = 0; j < 4; ++j) {
        float v0[4], v1[4];
        #pragma unroll
        for (int u = 0; u < 4; ++u) {
            float2 t = unp(acc[j][u]);
            float bb = sb2[tc * 4 + u];
            v0[u] = ftanh(t.x + bb);
            v1[u] = ftanh(t.y + bb);
        }
        int rg = row0 + tr * 8 + 2 * j;
        float* ep = g_enc + (size_t)rg * ENC + tc * 4;
        *(float4*)ep = make_float4(v0[0], v0[1], v0[2], v0[3]);
        ep += ENC;
        *(float4*)ep = make_float4(v1[0], v1[1], v1[2], v1[3]);
    }
}

// =====================================================================
// K4: distances/softmax (fp32) + 10 expert GEMMs via mma.sync bf16x3
// split (HMMA fragments pre-laid-out in smem), scalar second stage.
// 256 threads (8 warps), 1 CTA/SM.
// smem map:
//   [0, 66560)         encf [128e][130r] f32  -> later B frag double buffer:
//                        buf s at s*32768: hi 16KB | lo 16KB
//   [66560, 132096)    A frags: hi 32KB | lo 32KB
//                        (warp w, ktile kt, lane l) -> 4 u32 @ ((w*8+kt)*32+l)*4
//   [132096, 167936)   att [10][128] (dist phase) -> eh [128][70] f32
//   [167936, 173056)   sstr [10][128] f32
//   [173056, 179840)   Y double buffer (3392 B): we2 [64][12] | be1 | be2
//   [179840, 179904)   attn
// =====================================================================
#define AF_OFF   66560
#define EH_OFF   132096
#define SSTR_OFF 167936
#define Y_OFF    173056
#define ATTN_OFF 179840
#define K4_SMEM  179904

__global__ void __launch_bounds__(256) k4_fused(
    const float* __restrict__ We1, const float* __restrict__ be1,
    const float* __restrict__ We2, const float* __restrict__ be2,
    const float* __restrict__ attr, float* __restrict__ out)
{
    extern __shared__ __align__(16) char sm[];
    float* encf = (float*)sm;                       // e*130 + r
    float* att  = (float*)(sm + EH_OFF);            // [10][128] during dist phase
    float* ehp  = (float*)(sm + EH_OFF);            // [128][70] during expert loop
    float* sstr = (float*)(sm + SSTR_OFF);
    float* attn = (float*)(sm + ATTN_OFF);

    const int tid  = threadIdx.x;
    const int row0 = blockIdx.x * 128;
    const int r    = tid & 127, half = tid >> 7;
    const int lane = tid & 31,  w    = tid >> 5;
    const int g    = lane >> 2, t4   = lane & 3;

    // ---- load enc (transposed) + attractors ----
    for (int idx = tid; idx < 128 * 128; idx += 256) {
        int rr = idx >> 7, e = idx & 127;
        encf[e * 130 + rr] = g_enc[(size_t)(row0 + rr) * ENC + e];
    }
    for (int idx = tid; idx < NK * ENC; idx += 256) att[idx] = attr[idx];
    __syncthreads();
    if (tid < NK) {
        float s = 0.f;
        for (int e = 0; e < ENC; ++e) { float v = att[tid * ENC + e]; s += v * v; }
        attn[tid] = s;
    }
    __syncthreads();

    // ---- distances: 5 experts per half ----
    {
        float en = 0.f, dk[5] = {0.f, 0.f, 0.f, 0.f, 0.f};
        const float* ap = att + half * 5 * ENC;
        for (int e = 0; e < ENC; ++e) {
            float v = encf[e * 130 + r];
            en += v * v;
            #pragma unroll
            for (int q = 0; q < 5; ++q) dk[q] += v * ap[q * ENC + e];
        }
        #pragma unroll
        for (int q = 0; q < 5; ++q) {
            int k = half * 5 + q;
            float d2 = fmaxf(en + attn[k] - 2.f * dk[q], 0.f);
            sstr[k * 128 + r] = -2.f * sqrtf(d2);   // -dist/TEMP, TEMP=0.5
        }
    }
    __syncthreads();

    // ---- softmax (tid<128) ----
    if (tid < 128) {
        float v[NK], mx = -1e30f;
        #pragma unroll
        for (int k = 0; k < NK; ++k) { v[k] = sstr[k * 128 + tid]; mx = fmaxf(mx, v[k]); }
        float s = 0.f;
        #pragma unroll
        for (int k = 0; k < NK; ++k) { v[k] = __expf(v[k] - mx); s += v[k]; }
        float inv = __fdividef(1.f, s);
        #pragma unroll
        for (int k = 0; k < NK; ++k) sstr[k * 128 + tid] = v[k] * inv;
    }

    // ---- convert enc -> A fragments (hi/lo), m16n8k16 per-lane layout ----
    // slot = (warp ww, ktile kt, lane ll); rows r1=ww*16+gg, r2=r1+8; k cols e0=kt*16+2tt
    for (int slot = tid; slot < 2048; slot += 256) {
        int ll = slot & 31, kt = (slot >> 5) & 7, ww = slot >> 8;
        int gg = ll >> 2, tt = ll & 3;
        int r1 = ww * 16 + gg, r2 = r1 + 8;
        int e0 = kt * 16 + 2 * tt;
        float v00 = encf[e0 * 130 + r1],       v01 = encf[(e0 + 1) * 130 + r1];
        float v10 = encf[e0 * 130 + r2],       v11 = encf[(e0 + 1) * 130 + r2];
        float v02 = encf[(e0 + 8) * 130 + r1], v03 = encf[(e0 + 9) * 130 + r1];
        float v12 = encf[(e0 + 8) * 130 + r2], v13 = encf[(e0 + 9) * 130 + r2];
        u32 h0, l0, h1, l1, h2, l2, h3, l3;
        split2(v00, v01, h0, l0); split2(v10, v11, h1, l1);
        split2(v02, v03, h2, l2); split2(v12, v13, h3, l3);
        u32* AH = (u32*)(sm + AF_OFF)         + ((ww * 8 + kt) * 32 + ll) * 4;
        u32* AL = (u32*)(sm + AF_OFF + 32768) + ((ww * 8 + kt) * 32 + ll) * 4;
        AH[0] = h0; AH[1] = h1; AH[2] = h2; AH[3] = h3;
        AL[0] = l0; AL[1] = l1; AL[2] = l2; AL[3] = l3;
    }
    __syncthreads();   // encf (+att) dead -> B buffers / eh may overwrite

    // ---- staging: We1_k -> B fragments (hi/lo) + Y (we2/be1/be2) ----
    auto stage_B = [&](int kk) {
        u32* BH = (u32*)(sm + (kk & 1) * 32768);
        u32* BL = BH + 4096;
        const float* wsrc = We1 + (size_t)kk * ENC * EXPH;
        for (int slot = tid; slot < 2048; slot += 256) {
            int ll = slot & 31, nt = (slot >> 5) & 7, kt = slot >> 8;
            int gg = ll >> 2, tt = ll & 3;
            int n = nt * 8 + gg, e0 = kt * 16 + 2 * tt;
            float w00 = wsrc[e0 * 64 + n],       w01 = wsrc[(e0 + 1) * 64 + n];
            float w10 = wsrc[(e0 + 8) * 64 + n], w11 = wsrc[(e0 + 9) * 64 + n];
            u32 b0h, b0l, b1h, b1l;
            split2(w00, w01, b0h, b0l); split2(w10, w11, b1h, b1l);
            u32* p = BH + ((kt * 8 + nt) * 32 + ll) * 2; p[0] = b0h; p[1] = b1h;
            u32* q = BL + ((kt * 8 + nt) * 32 + ll) * 2; q[0] = b0l; q[1] = b1l;
        }
        float* yb = (float*)(sm + Y_OFF + (kk & 1) * 3392);
        for (int idx = tid; idx < EXPH * ACTD; idx += 256)
            yb[(idx / ACTD) * 12 + (idx % ACTD)] = We2[kk * EXPH * ACTD + idx];
        if (tid < EXPH) yb[768 + tid] = be1[kk * EXPH + tid];
        if (tid < ACTD) yb[832 + tid] = be2[kk * ACTD + tid];
    };

    stage_B(0);
    __syncthreads();

    float outacc[ACTD];
    #pragma unroll
    for (int a = 0; a < ACTD; ++a) outacc[a] = 0.f;

    for (int k = 0; k < NK; ++k) {
        // ---- phase A: eh = enc @ We1_k on HMMA, bf16x3 split ----
        float acc[8][4];
        #pragma unroll
        for (int nt = 0; nt < 8; ++nt)
            #pragma unroll
            for (int j = 0; j < 4; ++j) acc[nt][j] = 0.f;

        const u32* AH = (const u32*)(sm + AF_OFF);
        const u32* AL = (const u32*)(sm + AF_OFF + 32768);
        const u32* BH = (const u32*)(sm + (k & 1) * 32768);
        const u32* BL = BH + 4096;

        #pragma unroll
        for (int kt = 0; kt < 8; ++kt) {
            uint4 ah = *(const uint4*)(AH + ((w * 8 + kt) * 32 + lane) * 4);
            uint4 al = *(const uint4*)(AL + ((w * 8 + kt) * 32 + lane) * 4);
            uint2 bh[8], bl[8];
            #pragma unroll
            for (int nt = 0; nt < 8; ++nt) {
                bh[nt] = *(const uint2*)(BH + ((kt * 8 + nt) * 32 + lane) * 2);
                bl[nt] = *(const uint2*)(BL + ((kt * 8 + nt) * 32 + lane) * 2);
            }
            #pragma unroll
            for (int nt = 0; nt < 8; ++nt)
                mma_bf16(acc[nt], ah.x, ah.y, ah.z, ah.w, bh[nt].x, bh[nt].y);
            #pragma unroll
            for (int nt = 0; nt < 8; ++nt)
                mma_bf16(acc[nt], ah.x, ah.y, ah.z, ah.w, bl[nt].x, bl[nt].y);
            #pragma unroll
            for (int nt = 0; nt < 8; ++nt)
                mma_bf16(acc[nt], al.x, al.y, al.z, al.w, bh[nt].x, bh[nt].y);
        }

        // ---- store eh to smem with bias+relu ----
        const float* yb   = (const float*)(sm + Y_OFF + (k & 1) * 3392);
        const float* be1s = yb + 768;
        {
            int r1 = w * 16 + g, r2 = r1 + 8, c0 = 2 * t4;
            #pragma unroll
            for (int nt = 0; nt < 8; ++nt) {
                int h = nt * 8 + c0;
                float b0v = be1s[h], b1v = be1s[h + 1];
                *(float2*)(ehp + r1 * 70 + h) =
                    make_float2(fmaxf(acc[nt][0] + b0v, 0.f), fmaxf(acc[nt][1] + b1v, 0.f));
                *(float2*)(ehp + r2 * 70 + h) =
                    make_float2(fmaxf(acc[nt][2] + b0v, 0.f), fmaxf(acc[nt][3] + b1v, 0.f));
            }
        }
        __syncthreads();

        // ---- phase B: out += s_k*(eh @ We2_k + be2_k), h split by half ----
        {
            const float* be2s = yb + 832;
            float o[ACTD];
            #pragma unroll
            for (int a = 0; a < ACTD; ++a) o[a] = 0.f;
            #pragma unroll 8
            for (int c = 0; c < 32; ++c) {
                int h = half * 32 + c;
                float ev = ehp[r * 70 + h];
                const float* wp = yb + h * 12;
                float4 wa = *(const float4*)(wp);
                float4 wb = *(const float4*)(wp + 4);
                float4 wc = *(const float4*)(wp + 8);
                o[0] += ev * wa.x; o[1] += ev * wa.y; o[2] += ev * wa.z; o[3] += ev * wa.w;
                o[4] += ev * wb.x; o[5] += ev * wb.y; o[6] += ev * wb.z; o[7] += ev * wb.w;
                o[8] += ev * wc.x; o[9] += ev * wc.y;
            }
            float s = sstr[k * 128 + r];
            if (half == 0) {
                #pragma unroll
                for (int a = 0; a < ACTD; ++a) outacc[a] += s * (o[a] + be2s[a]);
            } else {
                #pragma unroll
                for (int a = 0; a < ACTD; ++a) outacc[a] += s * o[a];
            }
        }

        if (k + 1 < NK) stage_B(k + 1);
        __syncthreads();
    }

    // ---- combine halves via eh region (dead) and write out ----
    if (half == 1) {
        #pragma unroll
        for (int a = 0; a < ACTD; ++a) ehp[r * ACTD + a] = outacc[a];
    }
    __syncthreads();
    if (half == 0) {
        float* op = out + (size_t)(row0 + r) * ACTD;
        #pragma unroll
        for (int a = 0; a < ACTD; ++a) op[a] = outacc[a] + ehp[r * ACTD + a];
    }
}

// =====================================================================
extern "C" void kernel_launch(void* const* d_in, const int* in_sizes, int n_in,
                              void* d_out, int out_size)
{
    const float* state = (const float*)d_in[0];
    const float* W1    = (const float*)d_in[1];
    const float* b1    = (const float*)d_in[2];
    const float* gamma = (const float*)d_in[3];
    const float* beta  = (const float*)d_in[4];
    const float* W2    = (const float*)d_in[5];
    const float* b2    = (const float*)d_in[6];
    const float* We1   = (const float*)d_in[7];
    const float* be1   = (const float*)d_in[8];
    const float* We2   = (const float*)d_in[9];
    const float* be2   = (const float*)d_in[10];
    const float* attr  = (const float*)d_in[11];
    float* out = (float*)d_out;

    cudaFuncSetAttribute(k1_gemm_relu, cudaFuncAttributeMaxDynamicSharedMemorySize, K1_SMEM);
    cudaFuncSetAttribute(k3_gemm_tanh, cudaFuncAttributeMaxDynamicSharedMemorySize, K3_SMEM);
    cudaFuncSetAttribute(k4_fused,     cudaFuncAttributeMaxDynamicSharedMemorySize, K4_SMEM);

    k1_gemm_relu<<<dim3(GRID1, 2), 512, K1_SMEM>>>(state, W1, b1);
    k2_bnstats<<<HID, 256>>>(gamma, beta);
    k3_gemm_tanh<<<GRID1, 512, K3_SMEM>>>(W2, b2);
    k4_fused<<<GRID1, 256, K4_SMEM>>>(We1, be1, We2, be2, attr, out);
}